// round 13
// baseline (speedup 1.0000x reference)
#include <cuda_runtime.h>
#include <cstdint>

// Problem constants
#define BSZ   2
#define TLEN  2048
#define CDIM  1024
#define NH    16
#define HD    64
#define SCALE 0.125f   // 1/sqrt(64)

// Scratch (allocation-free rule: __device__ globals). tf32 bit patterns.
static __device__ uint32_t g_q[BSZ * NH * TLEN * HD];     // [B,H,T,D] (Q pre-scaled)
static __device__ uint32_t g_k[BSZ * NH * TLEN * HD];
static __device__ uint32_t g_v[BSZ * NH * TLEN * HD];
static __device__ uint32_t g_yt[BSZ * TLEN * CDIM];       // attn out, tf32 bits
static __device__ uint32_t g_xt[BSZ * TLEN * CDIM];       // x, tf32 bits [M,K]
static __device__ uint32_t g_wqkv32[CDIM * 3 * CDIM];     // Wqkv tf32 bits [K,N]
static __device__ uint32_t g_wo32[CDIM * CDIM];           // Wo tf32 bits [K,N]

extern __shared__ unsigned char SMEMRAW[];

// ---------------------------------------------------------------------------
// helpers
// ---------------------------------------------------------------------------
__device__ __forceinline__ uint32_t f2tf(float x) {
    uint32_t t;
    asm("cvt.rna.tf32.f32 %0, %1;" : "=r"(t) : "f"(x));
    return t;
}

__device__ __forceinline__ void mma_tf32(float c[4],
                                         const uint32_t a[4],
                                         uint32_t b0, uint32_t b1) {
    asm volatile(
        "mma.sync.aligned.m16n8k8.row.col.f32.tf32.tf32.f32 "
        "{%0,%1,%2,%3},{%4,%5,%6,%7},{%8,%9},{%0,%1,%2,%3};"
        : "+f"(c[0]), "+f"(c[1]), "+f"(c[2]), "+f"(c[3])
        : "r"(a[0]), "r"(a[1]), "r"(a[2]), "r"(a[3]), "r"(b0), "r"(b1));
}

__device__ __forceinline__ void cp16(void* s, const void* g) {
    uint32_t sa = (uint32_t)__cvta_generic_to_shared(s);
    asm volatile("cp.async.cg.shared.global [%0], [%1], 16;" :: "r"(sa), "l"(g));
}
__device__ __forceinline__ void cp_commit() {
    asm volatile("cp.async.commit_group;" ::: "memory");
}
template<int n>
__device__ __forceinline__ void cp_wait() {
    asm volatile("cp.async.wait_group %0;" :: "n"(n) : "memory");
}

// ---------------------------------------------------------------------------
// Prep kernels: fp32 -> tf32 bits (RNA). Destinations are the __device__
// globals referenced DIRECTLY in device code (never passed from host — a
// __device__ array's address is not valid in host code; that was the
// round-11/12 failure).
// ---------------------------------------------------------------------------
__global__ void cvt_x_kernel(const float* __restrict__ src) {
    const int i = blockIdx.x * blockDim.x + threadIdx.x;
    if (i < BSZ * TLEN * CDIM) g_xt[i] = f2tf(src[i]);
}
__global__ void cvt_wqkv_kernel(const float* __restrict__ src) {
    const int i = blockIdx.x * blockDim.x + threadIdx.x;
    if (i < 3 * CDIM * CDIM) g_wqkv32[i] = f2tf(src[i]);
}
__global__ void cvt_wo_kernel(const float* __restrict__ src) {
    const int i = blockIdx.x * blockDim.x + threadIdx.x;
    if (i < CDIM * CDIM) g_wo32[i] = f2tf(src[i]);
}

// ---------------------------------------------------------------------------
// tf32 GEMM core — EXACT round-8 structure (proven passing): 128x128 block
// tile, 8 warps (warp tile 64x32), K-chunk 16, 3-stage cp.async pipeline.
// Operands are pre-converted tf32 bits -> no cvt in the fragment-LDS path.
//   A [M,K] row-major tf32 bits;  W [K,N] row-major tf32 bits.
// As stride 20 (bank=4g+tig injective), Ws stride 136 (bank=8tig+g injective).
// ---------------------------------------------------------------------------
#define AS_STRIDE 20
#define WS_STRIDE 136
#define GSTAGE    3
#define AS_ELEMS  (128 * AS_STRIDE)
#define WS_ELEMS  (16 * WS_STRIDE)
#define GEMM_SMEM (GSTAGE * (AS_ELEMS + WS_ELEMS) * 4)

template<int N, int K>
__device__ __forceinline__ void gemm128_tf32(const uint32_t* __restrict__ A,
                                             const uint32_t* __restrict__ W,
                                             float acc[4][4][4])
{
    uint32_t* Asm = (uint32_t*)SMEMRAW;           // [GSTAGE][128*AS_STRIDE]
    uint32_t* Wsm = Asm + GSTAGE * AS_ELEMS;      // [GSTAGE][16*WS_STRIDE]

    const int tid  = threadIdx.x;
    const int warp = tid >> 5;
    const int lane = tid & 31;
    const int g    = lane >> 2;
    const int tig  = lane & 3;
    const int bm   = blockIdx.y * 128;
    const int bn   = blockIdx.x * 128;
    const int wm   = (warp & 1) * 64;
    const int wn   = (warp >> 1) * 32;

    const int am0 = tid >> 2;           // A row 0..63 (+64 for second)
    const int akq = (tid & 3) * 4;      // k offset
    const int wk0 = tid >> 5;           // W k-row 0..7 (+8 for second)
    const int wn4 = (tid & 31) * 4;     // n offset

    const uint32_t* Ap0 = A + (size_t)(bm + am0) * K + akq;
    const uint32_t* Ap1 = Ap0 + (size_t)64 * K;
    const uint32_t* Wp0 = W + (size_t)wk0 * N + bn + wn4;
    const uint32_t* Wp1 = Wp0 + (size_t)8 * N;

#pragma unroll
    for (int i = 0; i < 4; i++)
#pragma unroll
        for (int j = 0; j < 4; j++)
#pragma unroll
            for (int e = 0; e < 4; e++) acc[i][j][e] = 0.f;

    auto issue = [&](int c) {
        const int sl  = c % GSTAGE;
        const int off = c * 16;
        uint32_t* Ad = Asm + sl * AS_ELEMS;
        uint32_t* Wd = Wsm + sl * WS_ELEMS;
        cp16(Ad + am0 * AS_STRIDE + akq,        Ap0 + off);
        cp16(Ad + (am0 + 64) * AS_STRIDE + akq, Ap1 + off);
        cp16(Wd + wk0 * WS_STRIDE + wn4,        Wp0 + (size_t)off * N);
        cp16(Wd + (wk0 + 8) * WS_STRIDE + wn4,  Wp1 + (size_t)off * N);
        cp_commit();
    };

    issue(0);
    issue(1);

    const int NC = K / 16;
    for (int c = 0; c < NC; c++) {
        if (c + 2 < NC) issue(c + 2);
        const int rem = NC - 1 - c;
        if (rem >= 2)      cp_wait<2>();
        else if (rem == 1) cp_wait<1>();
        else               cp_wait<0>();
        __syncthreads();

        const uint32_t* Ab = Asm + (c % GSTAGE) * AS_ELEMS;
        const uint32_t* Wb = Wsm + (c % GSTAGE) * WS_ELEMS;
#pragma unroll
        for (int ks = 0; ks < 2; ks++) {
            const int kb = ks * 8;
            uint32_t af[4][4];
#pragma unroll
            for (int fm = 0; fm < 4; fm++) {
                const int r = wm + fm * 16 + g;
                af[fm][0] = Ab[r * AS_STRIDE + kb + tig];
                af[fm][1] = Ab[(r + 8) * AS_STRIDE + kb + tig];
                af[fm][2] = Ab[r * AS_STRIDE + kb + tig + 4];
                af[fm][3] = Ab[(r + 8) * AS_STRIDE + kb + tig + 4];
            }
            uint32_t bf[4][2];
#pragma unroll
            for (int fn = 0; fn < 4; fn++) {
                const int nn = wn + fn * 8 + g;
                bf[fn][0] = Wb[(kb + tig) * WS_STRIDE + nn];
                bf[fn][1] = Wb[(kb + tig + 4) * WS_STRIDE + nn];
            }
#pragma unroll
            for (int fm = 0; fm < 4; fm++)
#pragma unroll
                for (int fn = 0; fn < 4; fn++)
                    mma_tf32(acc[fm][fn], af[fm], bf[fn][0], bf[fn][1]);
        }
        __syncthreads();
    }
}

// ---------------------------------------------------------------------------
// Kernel 1: QKV projection; epilogue scatters tf32 bits into [B,H,T,D]
// ---------------------------------------------------------------------------
__global__ __launch_bounds__(256, 2) void qkv_gemm(const float* __restrict__ bias)
{
    float acc[4][4][4];
    gemm128_tf32<3 * CDIM, CDIM>(g_xt, g_wqkv32, acc);

    const int tid  = threadIdx.x;
    const int warp = tid >> 5;
    const int lane = tid & 31;
    const int g    = lane >> 2;
    const int tig  = lane & 3;
    const int bm   = blockIdx.y * 128;
    const int bn   = blockIdx.x * 128;
    const int wm   = (warp & 1) * 64;
    const int wn   = (warp >> 1) * 32;

#pragma unroll
    for (int fm = 0; fm < 4; fm++) {
#pragma unroll
        for (int fn = 0; fn < 4; fn++) {
            const int row0 = bm + wm + fm * 16 + g;
            const int col0 = bn + wn + fn * 8 + tig * 2;
#pragma unroll
            for (int e = 0; e < 4; e++) {
                const int m = row0 + (e >> 1) * 8;
                const int n = col0 + (e & 1);
                float v = acc[fm][fn][e] + __ldg(&bias[n]);
                const int bb    = m >> 11;
                const int t     = m & 2047;
                const int which = n >> 10;
                const int rem   = n & 1023;
                const int h     = rem >> 6;
                const int d     = rem & 63;
                if (which == 0) v *= SCALE;
                uint32_t* dst = (which == 0) ? g_q : (which == 1) ? g_k : g_v;
                dst[((bb * NH + h) * TLEN + t) * HD + d] = f2tf(v);
            }
        }
    }
}

// ---------------------------------------------------------------------------
// Kernel 3: output projection + bias, fp32 out
// ---------------------------------------------------------------------------
__global__ __launch_bounds__(256, 2) void out_gemm(const float* __restrict__ bias,
                                                   float* __restrict__ C)
{
    float acc[4][4][4];
    gemm128_tf32<CDIM, CDIM>(g_yt, g_wo32, acc);

    const int tid  = threadIdx.x;
    const int warp = tid >> 5;
    const int lane = tid & 31;
    const int g    = lane >> 2;
    const int tig  = lane & 3;
    const int bm   = blockIdx.y * 128;
    const int bn   = blockIdx.x * 128;
    const int wm   = (warp & 1) * 64;
    const int wn   = (warp >> 1) * 32;

#pragma unroll
    for (int fm = 0; fm < 4; fm++) {
#pragma unroll
        for (int fn = 0; fn < 4; fn++) {
            const int row0 = bm + wm + fm * 16 + g;
            const int col0 = bn + wn + fn * 8 + tig * 2;
            const float b0 = __ldg(&bias[col0]);
            const float b1 = __ldg(&bias[col0 + 1]);
            C[(size_t)row0 * CDIM + col0]           = acc[fm][fn][0] + b0;
            C[(size_t)row0 * CDIM + col0 + 1]       = acc[fm][fn][1] + b1;
            C[(size_t)(row0 + 8) * CDIM + col0]     = acc[fm][fn][2] + b0;
            C[(size_t)(row0 + 8) * CDIM + col0 + 1] = acc[fm][fn][3] + b1;
        }
    }
}

// ---------------------------------------------------------------------------
// Kernel 2: tensor-core flash attention (round-8 verbatim), inverted-causal
// mask (keep k >= q); epilogue writes tf32 bits to g_yt for out_gemm.
// ---------------------------------------------------------------------------
#define KS_STRIDE 68   // bank = 4g+tig  (injective)
#define VS_STRIDE 72   // bank = 8tig+g  (injective)
#define KS_ELEMS  (64 * KS_STRIDE)
#define VS_ELEMS  (64 * VS_STRIDE)
#define ATTN_SMEM ((2 * KS_ELEMS + 2 * VS_ELEMS) * 4)

__global__ __launch_bounds__(128, 3) void attn_kernel()
{
    uint32_t* Ksm = (uint32_t*)SMEMRAW;
    uint32_t* Vsm = Ksm + 2 * KS_ELEMS;

    const int tid  = threadIdx.x;
    const int warp = tid >> 5;
    const int lane = tid & 31;
    const int g    = lane >> 2;
    const int tig  = lane & 3;
    const int bh   = blockIdx.y;
    const int qt   = gridDim.x - 1 - blockIdx.x;       // heavy tiles first
    const int q0   = qt * 64;
    const int nIter = (TLEN - q0) >> 6;

    const uint32_t* Qb = g_q + (size_t)bh * TLEN * HD;
    const uint32_t* Kb = g_k + (size_t)bh * TLEN * HD;
    const uint32_t* Vb = g_v + (size_t)bh * TLEN * HD;

    auto issue = [&](int it) {
        const int k0 = q0 + it * 64;
        uint32_t* Kd = Ksm + (it & 1) * KS_ELEMS;
        uint32_t* Vd = Vsm + (it & 1) * VS_ELEMS;
#pragma unroll
        for (int i = 0; i < 8; i++) {
            const int idx = tid + i * 128;
            const int r = idx >> 4;
            const int c = (idx & 15) << 2;
            cp16(Kd + r * KS_STRIDE + c, Kb + (size_t)(k0 + r) * HD + c);
            cp16(Vd + r * VS_STRIDE + c, Vb + (size_t)(k0 + r) * HD + c);
        }
        cp_commit();
    };

    issue(0);

    const int row_lo = q0 + warp * 16 + g;

    uint32_t aQ[8][4];
#pragma unroll
    for (int kk = 0; kk < 8; kk++) {
        aQ[kk][0] = Qb[(size_t)row_lo * HD + kk * 8 + tig];
        aQ[kk][1] = Qb[(size_t)(row_lo + 8) * HD + kk * 8 + tig];
        aQ[kk][2] = Qb[(size_t)row_lo * HD + kk * 8 + tig + 4];
        aQ[kk][3] = Qb[(size_t)(row_lo + 8) * HD + kk * 8 + tig + 4];
    }

    float o[8][4];
#pragma unroll
    for (int dn = 0; dn < 8; dn++)
#pragma unroll
        for (int e = 0; e < 4; e++) o[dn][e] = 0.f;
    float mrow[2] = {-1e30f, -1e30f};
    float lrow[2] = {0.f, 0.f};

    for (int it = 0; it < nIter; it++) {
        if (it + 1 < nIter) { issue(it + 1); cp_wait<1>(); }
        else                cp_wait<0>();
        __syncthreads();

        const uint32_t* Ks = Ksm + (it & 1) * KS_ELEMS;
        const uint32_t* Vs = Vsm + (it & 1) * VS_ELEMS;

        float s[8][4];
#pragma unroll
        for (int fn = 0; fn < 8; fn++) {
#pragma unroll
            for (int e = 0; e < 4; e++) s[fn][e] = 0.f;
#pragma unroll
            for (int kk = 0; kk < 8; kk++) {
                const uint32_t b0 = Ks[(fn * 8 + g) * KS_STRIDE + kk * 8 + tig];
                const uint32_t b1 = Ks[(fn * 8 + g) * KS_STRIDE + kk * 8 + tig + 4];
                mma_tf32(s[fn], aQ[kk], b0, b1);
            }
        }

        if (it == 0) {
#pragma unroll
            for (int fn = 0; fn < 8; fn++)
#pragma unroll
                for (int e = 0; e < 4; e++) {
                    const int key = fn * 8 + tig * 2 + (e & 1);
                    const int qr  = warp * 16 + g + ((e >> 1) << 3);
                    if (key < qr) s[fn][e] = -1e30f;   // keep k >= q
                }
        }

        float rm0 = -1e30f, rm1 = -1e30f;
#pragma unroll
        for (int fn = 0; fn < 8; fn++) {
            rm0 = fmaxf(rm0, fmaxf(s[fn][0], s[fn][1]));
            rm1 = fmaxf(rm1, fmaxf(s[fn][2], s[fn][3]));
        }
        rm0 = fmaxf(rm0, __shfl_xor_sync(0xffffffffu, rm0, 1));
        rm0 = fmaxf(rm0, __shfl_xor_sync(0xffffffffu, rm0, 2));
        rm1 = fmaxf(rm1, __shfl_xor_sync(0xffffffffu, rm1, 1));
        rm1 = fmaxf(rm1, __shfl_xor_sync(0xffffffffu, rm1, 2));

        const float mn0 = fmaxf(mrow[0], rm0);
        const float mn1 = fmaxf(mrow[1], rm1);
        const float c0 = __expf(mrow[0] - mn0);
        const float c1 = __expf(mrow[1] - mn1);
        mrow[0] = mn0; mrow[1] = mn1;
        lrow[0] *= c0; lrow[1] *= c1;
#pragma unroll
        for (int dn = 0; dn < 8; dn++) {
            o[dn][0] *= c0; o[dn][1] *= c0;
            o[dn][2] *= c1; o[dn][3] *= c1;
        }

        float ps0 = 0.f, ps1 = 0.f;
#pragma unroll
        for (int fn = 0; fn < 8; fn++) {
            s[fn][0] = __expf(s[fn][0] - mn0);
            s[fn][1] = __expf(s[fn][1] - mn0);
            s[fn][2] = __expf(s[fn][2] - mn1);
            s[fn][3] = __expf(s[fn][3] - mn1);
            ps0 += s[fn][0] + s[fn][1];
            ps1 += s[fn][2] + s[fn][3];
        }
        ps0 += __shfl_xor_sync(0xffffffffu, ps0, 1);
        ps0 += __shfl_xor_sync(0xffffffffu, ps0, 2);
        ps1 += __shfl_xor_sync(0xffffffffu, ps1, 1);
        ps1 += __shfl_xor_sync(0xffffffffu, ps1, 2);
        lrow[0] += ps0; lrow[1] += ps1;

        const int src1 = (g << 2) + (tig >> 1);
        const int src2 = src1 + 2;
        const bool odd = (tig & 1) != 0;
#pragma unroll
        for (int fn = 0; fn < 8; fn++) {
            const float x0 = __shfl_sync(0xffffffffu, s[fn][0], src1);
            const float x1 = __shfl_sync(0xffffffffu, s[fn][1], src1);
            const float x2 = __shfl_sync(0xffffffffu, s[fn][2], src1);
            const float x3 = __shfl_sync(0xffffffffu, s[fn][3], src1);
            const float y0 = __shfl_sync(0xffffffffu, s[fn][0], src2);
            const float y1 = __shfl_sync(0xffffffffu, s[fn][1], src2);
            const float y2 = __shfl_sync(0xffffffffu, s[fn][2], src2);
            const float y3 = __shfl_sync(0xffffffffu, s[fn][3], src2);
            uint32_t ap[4];
            ap[0] = f2tf(odd ? x1 : x0);
            ap[1] = f2tf(odd ? x3 : x2);
            ap[2] = f2tf(odd ? y1 : y0);
            ap[3] = f2tf(odd ? y3 : y2);
#pragma unroll
            for (int dn = 0; dn < 8; dn++) {
                const uint32_t b0 = Vs[(fn * 8 + tig) * VS_STRIDE + dn * 8 + g];
                const uint32_t b1 = Vs[(fn * 8 + tig + 4) * VS_STRIDE + dn * 8 + g];
                mma_tf32(o[dn], ap, b0, b1);
            }
        }
        __syncthreads();
    }

    // epilogue: normalize, write tf32 bits to g_yt [B,T,C]
    const int b = bh >> 4;
    const int h = bh & 15;
    const float inv0 = 1.f / lrow[0];
    const float inv1 = 1.f / lrow[1];
    uint32_t* yp0 = g_yt + ((size_t)(b * TLEN + row_lo)) * CDIM + h * HD;
    uint32_t* yp1 = yp0 + (size_t)8 * CDIM;
#pragma unroll
    for (int dn = 0; dn < 8; dn++) {
        uint2 v0, v1;
        v0.x = f2tf(o[dn][0] * inv0); v0.y = f2tf(o[dn][1] * inv0);
        v1.x = f2tf(o[dn][2] * inv1); v1.y = f2tf(o[dn][3] * inv1);
        *(uint2*)(yp0 + dn * 8 + tig * 2) = v0;
        *(uint2*)(yp1 + dn * 8 + tig * 2) = v1;
    }
}

// ---------------------------------------------------------------------------
extern "C" void kernel_launch(void* const* d_in, const int* in_sizes, int n_in,
                              void* d_out, int out_size)
{
    const float* x    = (const float*)d_in[0];
    const float* Wqkv = (const float*)d_in[1];
    const float* bqkv = (const float*)d_in[2];
    const float* Wo   = (const float*)d_in[3];
    const float* bo   = (const float*)d_in[4];
    float* out = (float*)d_out;

    cudaFuncSetAttribute(qkv_gemm,    cudaFuncAttributeMaxDynamicSharedMemorySize, GEMM_SMEM);
    cudaFuncSetAttribute(out_gemm,    cudaFuncAttributeMaxDynamicSharedMemorySize, GEMM_SMEM);
    cudaFuncSetAttribute(attn_kernel, cudaFuncAttributeMaxDynamicSharedMemorySize, ATTN_SMEM);

    // prep: tf32 conversions (destinations referenced inside the kernels)
    cvt_x_kernel<<<(BSZ * TLEN * CDIM + 255) / 256, 256>>>(x);
    cvt_wqkv_kernel<<<(3 * CDIM * CDIM + 255) / 256, 256>>>(Wqkv);
    cvt_wo_kernel<<<(CDIM * CDIM + 255) / 256, 256>>>(Wo);

    qkv_gemm<<<dim3(24, 32), 256, GEMM_SMEM>>>(bqkv);     // N=3072/128, M=4096/128
    attn_kernel<<<dim3(32, 32), 128, ATTN_SMEM>>>();
    out_gemm<<<dim3(8, 32), 256, GEMM_SMEM>>>(bo, out);   // N=1024/128, M=4096/128
}